// round 4
// baseline (speedup 1.0000x reference)
#include <cuda_runtime.h>

// Problem geometry (fixed by the dataset)
#define W     1920
#define H     1080
#define NPL   6            // B*C planes
#define HWSZ  (H*W)
#define NTOT  (NPL*HWSZ)   // 12,441,600
#define KS    51
#define RAD   25
#define W2    (W/2)

typedef unsigned long long u64;   // container for packed f32x2

// Scratch (allocation-free rule: __device__ globals)
__device__ float g_tmpA[NTOT];
__device__ float g_tmpB[NTOT];
__device__ float g_tmpC[NTOT];
__device__ float g_k1[KS];

// ---- packed f32x2 helpers (Blackwell) ----
__device__ __forceinline__ u64 pack2(float x, float y) {
    u64 r; asm("mov.b64 %0, {%1, %2};" : "=l"(r) : "f"(x), "f"(y)); return r;
}
__device__ __forceinline__ void unpack2(u64 v, float& x, float& y) {
    asm("mov.b64 {%0, %1}, %2;" : "=f"(x), "=f"(y) : "l"(v));
}
__device__ __forceinline__ u64 fma2(u64 a, u64 b, u64 c) {
    u64 d; asm("fma.rn.f32x2 %0, %1, %2, %3;" : "=l"(d) : "l"(a), "l"(b), "l"(c));
    return d;
}

// --- 1D kernel extraction: 2D kernel is outer product k1*k1^T with sum(k1)=1,
// so row-sums recover k1 exactly (up to fp32 rounding). ---
__global__ void k1d_kernel(const float* __restrict__ k2d) {
    int i = threadIdx.x;
    if (i < KS) {
        float s = 0.f;
        #pragma unroll
        for (int j = 0; j < KS; j++) s += k2d[i * KS + j];
        g_k1[i] = s;
    }
}

__device__ __forceinline__ int reflect_idx(int i, int n) {
    // jnp.pad mode='reflect' (mirror WITHOUT repeating the edge)
    if (i < 0)  i = -i;
    if (i >= n) i = 2 * n - 2 - i;
    return i;
}

// ======================= Horizontal conv (row-paired f32x2) =================
// Block: 128 threads (4 warps). Each warp covers 160 consecutive x
// (lane + 32*r, r<5). Block tile = 640 x-cols, 2 rows. 1920 = 3*640 exact.
#define HR    5
#define HSPAN (4 * 32 * HR)      // 640
#define HWIN  (HSPAN + 2 * RAD)  // 690

__global__ void hconv2_kernel(const float* __restrict__ in, float* __restrict__ out) {
    __shared__ u64 s2[HWIN];
    __shared__ u64 kk2[KS];
    const int tid  = threadIdx.x;
    const int lane = tid & 31, warp = tid >> 5;
    const int rp = blockIdx.y;              // row pair 0..NPL*H/2-1
    const int x0 = blockIdx.x * HSPAN;
    const float* r0 = in + (size_t)(2 * rp) * W;
    const float* r1 = r0 + W;

    if (tid < KS) { float k = g_k1[tid]; kk2[tid] = pack2(k, k); }
    for (int i = tid; i < HWIN; i += 128) {
        int x = reflect_idx(x0 - RAD + i, W);
        s2[i] = pack2(r0[x], r1[x]);
    }
    __syncthreads();

    u64 acc[HR];
    #pragma unroll
    for (int r = 0; r < HR; r++) acc[r] = 0ull;   // (0.f, 0.f)

    const int base = warp * (32 * HR) + lane;
    #pragma unroll
    for (int t = 0; t < KS; t++) {
        u64 k = kk2[t];
        #pragma unroll
        for (int r = 0; r < HR; r++)
            acc[r] = fma2(k, s2[base + 32 * r + t], acc[r]);
    }

    float* o0 = out + (size_t)(2 * rp) * W;
    float* o1 = o0 + W;
    #pragma unroll
    for (int r = 0; r < HR; r++) {
        int x = x0 + base + 32 * r;          // always < W (exact tiling)
        float a, b; unpack2(acc[r], a, b);
        o0[x] = a; o1[x] = b;
    }
}

// ================= Vertical conv (column-paired f32x2) ======================
// Block (32,8): 32 lanes = 32 float2 columns (64 scalar cols), each thread
// computes 8 consecutive y rows -> 64 rows per block.
#define VR    8
#define VTH   64
#define VWIN  (VTH + 2 * RAD)    // 114

// Pass 3: blur = Vconv(tmpA); fused residual/mask.
__global__ void vconv_mask2_kernel(const u64* __restrict__ in,
                                   const u64* __restrict__ img,
                                   u64* __restrict__ blur_out,
                                   u64* __restrict__ mask_out) {
    __shared__ u64 s2[VWIN][32];
    __shared__ u64 kk2[KS];
    const int tx = threadIdx.x, ty = threadIdx.y;
    const int tid = ty * 32 + tx;
    const int c  = blockIdx.x * 32 + tx;     // float2 column index, < W2
    const int y0 = blockIdx.y * VTH;
    const size_t pb = (size_t)blockIdx.z * (HWSZ / 2);

    if (tid < KS) { float k = g_k1[tid]; kk2[tid] = pack2(k, k); }
    for (int i = ty; i < VWIN; i += 8) {
        int y = reflect_idx(y0 - RAD + i, H);
        s2[i][tx] = in[pb + (size_t)y * W2 + c];
    }
    __syncthreads();

    u64 acc[VR];
    #pragma unroll
    for (int r = 0; r < VR; r++) acc[r] = 0ull;

    const int yb = ty * VR;
    #pragma unroll
    for (int t = 0; t < KS; t++) {
        u64 k = kk2[t];
        #pragma unroll
        for (int r = 0; r < VR; r++)
            acc[r] = fma2(k, s2[yb + r + t][tx], acc[r]);
    }

    #pragma unroll
    for (int r = 0; r < VR; r++) {
        int y = y0 + yb + r;
        if (y < H) {
            size_t idx = pb + (size_t)y * W2 + c;
            float bx, by, ix, iy;
            unpack2(acc[r], bx, by);
            unpack2(img[idx], ix, iy);
            blur_out[idx] = acc[r];
            float mx = (fabsf(ix - bx) * 255.0f > 10.0f) ? 1.0f : 0.0f;
            float my = (fabsf(iy - by) * 255.0f > 10.0f) ? 1.0f : 0.0f;
            mask_out[idx] = pack2(mx, my);
        }
    }
}

// Pass 5: soft_mask = Vconv(tmpC); fused final blend. blur read/written in the
// same buffer at the same index per thread -> no restrict on that pointer.
__global__ void vconv_final2_kernel(const u64* __restrict__ in,
                                    const u64* __restrict__ img,
                                    u64* blur_and_out) {
    __shared__ u64 s2[VWIN][32];
    __shared__ u64 kk2[KS];
    const int tx = threadIdx.x, ty = threadIdx.y;
    const int tid = ty * 32 + tx;
    const int c  = blockIdx.x * 32 + tx;
    const int y0 = blockIdx.y * VTH;
    const size_t pb = (size_t)blockIdx.z * (HWSZ / 2);

    if (tid < KS) { float k = g_k1[tid]; kk2[tid] = pack2(k, k); }
    for (int i = ty; i < VWIN; i += 8) {
        int y = reflect_idx(y0 - RAD + i, H);
        s2[i][tx] = in[pb + (size_t)y * W2 + c];
    }
    __syncthreads();

    u64 acc[VR];
    #pragma unroll
    for (int r = 0; r < VR; r++) acc[r] = 0ull;

    const int yb = ty * VR;
    #pragma unroll
    for (int t = 0; t < KS; t++) {
        u64 k = kk2[t];
        #pragma unroll
        for (int r = 0; r < VR; r++)
            acc[r] = fma2(k, s2[yb + r + t][tx], acc[r]);
    }

    #pragma unroll
    for (int r = 0; r < VR; r++) {
        int y = y0 + yb + r;
        if (y < H) {
            size_t idx = pb + (size_t)y * W2 + c;
            float sx, sy, ix, iy, bx, by;
            unpack2(acc[r], sx, sy);
            unpack2(img[idx], ix, iy);
            unpack2(blur_and_out[idx], bx, by);
            float shx = fminf(fmaxf(fmaf(0.5f, ix - bx, ix), 0.0f), 1.0f);
            float shy = fminf(fmaxf(fmaf(0.5f, iy - by, iy), 0.0f), 1.0f);
            float ox = sx * shx + (1.0f - sx) * ix;
            float oy = sy * shy + (1.0f - sy) * iy;
            blur_and_out[idx] = pack2(ox, oy);
        }
    }
}

extern "C" void kernel_launch(void* const* d_in, const int* in_sizes, int n_in,
                              void* d_out, int out_size) {
    const float* img = (const float*)d_in[0];   // [2,3,1080,1920] fp32
    const float* k2d = (const float*)d_in[1];   // [51,51] fp32
    float* out = (float*)d_out;

    float *tmpA, *tmpB, *tmpC;
    cudaGetSymbolAddress((void**)&tmpA, g_tmpA);
    cudaGetSymbolAddress((void**)&tmpB, g_tmpB);
    cudaGetSymbolAddress((void**)&tmpC, g_tmpC);

    // 1) recover 1D kernel
    k1d_kernel<<<1, 64>>>(k2d);

    dim3 hgrid(W / HSPAN, NPL * H / 2);          // (3, 3240)
    dim3 vgrid(W2 / 32, (H + VTH - 1) / VTH, NPL); // (30, 17, 6)
    dim3 vblk(32, 8);

    // 2) horizontal blur of img
    hconv2_kernel<<<hgrid, 128>>>(img, tmpA);
    // 3) vertical blur -> blur (d_out) + mask (tmpB)
    vconv_mask2_kernel<<<vgrid, vblk>>>((const u64*)tmpA, (const u64*)img,
                                        (u64*)out, (u64*)tmpB);
    // 4) horizontal blur of mask
    hconv2_kernel<<<hgrid, 128>>>(tmpB, tmpC);
    // 5) vertical blur of mask + final blend -> d_out
    vconv_final2_kernel<<<vgrid, vblk>>>((const u64*)tmpC, (const u64*)img,
                                         (u64*)out);
}

// round 5
// speedup vs baseline: 2.4146x; 2.4146x over previous
#include <cuda_runtime.h>

// Problem geometry (fixed by the dataset)
#define W     1920
#define H     1080
#define NPL   6            // B*C planes
#define HWSZ  (H*W)
#define NTOT  (NPL*HWSZ)   // 12,441,600
#define KS    51
#define RAD   25

// Scratch (allocation-free rule: __device__ globals)
__device__ float g_tmpA[NTOT];
__device__ float g_tmpB[NTOT];
__device__ float g_tmpC[NTOT];
__device__ float g_k1[KS];

// --- 1D kernel extraction: 2D kernel is outer product k1*k1^T with sum(k1)=1,
// so row-sums recover k1 exactly (up to fp32 rounding). ---
__global__ void k1d_kernel(const float* __restrict__ k2d) {
    int i = threadIdx.x;
    if (i < KS) {
        float s = 0.f;
        #pragma unroll
        for (int j = 0; j < KS; j++) s += k2d[i * KS + j];
        g_k1[i] = s;
    }
}

__device__ __forceinline__ int reflect_idx(int i, int n) {
    // jnp.pad mode='reflect' (mirror WITHOUT repeating the edge)
    if (i < 0)  i = -i;
    if (i >= n) i = 2 * n - 2 - i;
    return i;
}

// ================= Horizontal conv: sliding-window, R=5 =====================
// Block = 8 warps. Each warp owns ONE image row and a 160-wide x-tile
// (32 lanes x 5 consecutive outputs). 1920 = 12 * 160 exact.
// Lane output base o = 5*lane -> data LDS addresses 5*lane + t: gcd(5,32)=1,
// conflict-free. Weight LDS is a warp broadcast.
#define HR     5
#define HTILE  (32 * HR)          // 160
#define HWARPS 8
#define HWIN   (HTILE + 2 * RAD)  // 210

__global__ void __launch_bounds__(256) hconv_kernel(const float* __restrict__ in,
                                                    float* __restrict__ out) {
    __shared__ float sk[KS];
    __shared__ float srow[HWARPS][HWIN + 2];
    const int tid = threadIdx.x, lane = tid & 31, wp = tid >> 5;
    const int row = blockIdx.y * HWARPS + wp;       // 6480 rows, exact
    const int x0  = blockIdx.x * HTILE;

    if (tid < KS) sk[tid] = g_k1[tid];
    __syncthreads();

    const float* rin = in + (size_t)row * W;
    for (int i = lane; i < HWIN; i += 32)
        srow[wp][i] = rin[reflect_idx(x0 - RAD + i, W)];
    __syncwarp();

    const int o = lane * HR;
    float w[HR], acc[HR];
    #pragma unroll
    for (int j = 0; j < HR; j++) { w[j] = srow[wp][o + j]; acc[j] = 0.f; }

    #pragma unroll
    for (int t = 0; t < KS; t++) {
        float k = sk[t];
        #pragma unroll
        for (int r = 0; r < HR; r++) acc[r] = fmaf(k, w[r], acc[r]);
        if (t < KS - 1) {
            #pragma unroll
            for (int j = 0; j < HR - 1; j++) w[j] = w[j + 1];
            w[HR - 1] = srow[wp][o + t + HR];
        }
    }

    float* ro = out + (size_t)row * W + x0 + o;
    #pragma unroll
    for (int r = 0; r < HR; r++) ro[r] = acc[r];
}

// ================= Vertical conv: sliding-window, R=8 =======================
// Block (32,8): lanes = 32 consecutive x columns (coalesced, conflict-free
// smem: lanes index [tx]); each thread computes 8 consecutive y outputs via a
// register window sliding down the column. Block covers 64 rows.
#define VR    8
#define VTY   8
#define VTILE (VR * VTY)          // 64
#define VWIN  (VTILE + 2 * RAD)   // 114

// Pass 3: blur = Vconv(tmpA); fused residual/mask. blur->d_out, mask->tmpB.
__global__ void __launch_bounds__(256) vconv_mask_kernel(const float* __restrict__ in,
                                                         const float* __restrict__ img,
                                                         float* __restrict__ blur_out,
                                                         float* __restrict__ mask_out) {
    __shared__ float sk[KS];
    __shared__ float st[VWIN][32];
    const int tx = threadIdx.x, ty = threadIdx.y;
    const int tid = ty * 32 + tx;
    const int x  = blockIdx.x * 32 + tx;
    const int y0 = blockIdx.y * VTILE;
    const size_t pb = (size_t)blockIdx.z * HWSZ;

    if (tid < KS) sk[tid] = g_k1[tid];
    for (int i = ty; i < VWIN; i += VTY) {
        int y = reflect_idx(y0 - RAD + i, H);
        st[i][tx] = in[pb + (size_t)y * W + x];
    }
    __syncthreads();

    const int yb = ty * VR;
    float w[VR], acc[VR];
    #pragma unroll
    for (int j = 0; j < VR; j++) { w[j] = st[yb + j][tx]; acc[j] = 0.f; }

    #pragma unroll
    for (int t = 0; t < KS; t++) {
        float k = sk[t];
        #pragma unroll
        for (int r = 0; r < VR; r++) acc[r] = fmaf(k, w[r], acc[r]);
        if (t < KS - 1) {
            #pragma unroll
            for (int j = 0; j < VR - 1; j++) w[j] = w[j + 1];
            w[VR - 1] = st[yb + t + VR][tx];
        }
    }

    #pragma unroll
    for (int r = 0; r < VR; r++) {
        int y = y0 + yb + r;
        if (y < H) {
            size_t idx = pb + (size_t)y * W + x;
            float im = img[idx];
            blur_out[idx] = acc[r];
            mask_out[idx] = (fabsf(im - acc[r]) * 255.0f > 10.0f) ? 1.0f : 0.0f;
        }
    }
}

// Pass 5: soft_mask = Vconv(tmpC); fused final blend. blur read/written in the
// same buffer at the same index per thread -> no restrict on that pointer.
__global__ void __launch_bounds__(256) vconv_final_kernel(const float* __restrict__ in,
                                                          const float* __restrict__ img,
                                                          float* blur_and_out) {
    __shared__ float sk[KS];
    __shared__ float st[VWIN][32];
    const int tx = threadIdx.x, ty = threadIdx.y;
    const int tid = ty * 32 + tx;
    const int x  = blockIdx.x * 32 + tx;
    const int y0 = blockIdx.y * VTILE;
    const size_t pb = (size_t)blockIdx.z * HWSZ;

    if (tid < KS) sk[tid] = g_k1[tid];
    for (int i = ty; i < VWIN; i += VTY) {
        int y = reflect_idx(y0 - RAD + i, H);
        st[i][tx] = in[pb + (size_t)y * W + x];
    }
    __syncthreads();

    const int yb = ty * VR;
    float w[VR], acc[VR];
    #pragma unroll
    for (int j = 0; j < VR; j++) { w[j] = st[yb + j][tx]; acc[j] = 0.f; }

    #pragma unroll
    for (int t = 0; t < KS; t++) {
        float k = sk[t];
        #pragma unroll
        for (int r = 0; r < VR; r++) acc[r] = fmaf(k, w[r], acc[r]);
        if (t < KS - 1) {
            #pragma unroll
            for (int j = 0; j < VR - 1; j++) w[j] = w[j + 1];
            w[VR - 1] = st[yb + t + VR][tx];
        }
    }

    #pragma unroll
    for (int r = 0; r < VR; r++) {
        int y = y0 + yb + r;
        if (y < H) {
            size_t idx = pb + (size_t)y * W + x;
            float im = img[idx];
            float bl = blur_and_out[idx];
            float sharp = fminf(fmaxf(fmaf(0.5f, im - bl, im), 0.0f), 1.0f);
            blur_and_out[idx] = acc[r] * sharp + (1.0f - acc[r]) * im;
        }
    }
}

extern "C" void kernel_launch(void* const* d_in, const int* in_sizes, int n_in,
                              void* d_out, int out_size) {
    const float* img = (const float*)d_in[0];   // [2,3,1080,1920] fp32
    const float* k2d = (const float*)d_in[1];   // [51,51] fp32
    float* out = (float*)d_out;

    float *tmpA, *tmpB, *tmpC;
    cudaGetSymbolAddress((void**)&tmpA, g_tmpA);
    cudaGetSymbolAddress((void**)&tmpB, g_tmpB);
    cudaGetSymbolAddress((void**)&tmpC, g_tmpC);

    // 1) recover 1D kernel
    k1d_kernel<<<1, 64>>>(k2d);

    dim3 hgrid(W / HTILE, NPL * H / HWARPS);            // (12, 810)
    dim3 vgrid(W / 32, (H + VTILE - 1) / VTILE, NPL);   // (60, 17, 6)
    dim3 vblk(32, VTY);

    // 2) horizontal blur of img
    hconv_kernel<<<hgrid, 256>>>(img, tmpA);
    // 3) vertical blur -> blur (d_out) + mask (tmpB)
    vconv_mask_kernel<<<vgrid, vblk>>>(tmpA, img, out, tmpB);
    // 4) horizontal blur of mask
    hconv_kernel<<<hgrid, 256>>>(tmpB, tmpC);
    // 5) vertical blur of mask + final blend -> d_out
    vconv_final_kernel<<<vgrid, vblk>>>(tmpC, img, out);
}

// round 6
// speedup vs baseline: 3.1193x; 1.2918x over previous
#include <cuda_runtime.h>

// Problem geometry (fixed by the dataset)
#define W     1920
#define H     1080
#define NPL   6            // B*C planes
#define HWSZ  (H*W)
#define NTOT  (NPL*HWSZ)   // 12,441,600
#define KS    51
#define RAD   25
#define W2    (W/2)        // 960 u64 columns

typedef unsigned long long u64;   // packed f32x2

// Scratch (allocation-free rule: __device__ globals)
__device__ float g_tmpA[NTOT];
__device__ float g_tmpB[NTOT];
__device__ float g_tmpC[NTOT];
__device__ u64   g_kpair[KS];
__constant__ u64 c_kpair[KS];     // (k,k) pairs -> LDCU uniform path, off crossbar

// ---- packed f32x2 helpers (sm_103a) ----
__device__ __forceinline__ u64 pack2(float x, float y) {
    u64 r; asm("mov.b64 %0, {%1, %2};" : "=l"(r) : "f"(x), "f"(y)); return r;
}
__device__ __forceinline__ void unpack2(u64 v, float& x, float& y) {
    asm("mov.b64 {%0, %1}, %2;" : "=f"(x), "=f"(y) : "l"(v));
}
__device__ __forceinline__ u64 fma2(u64 a, u64 b, u64 c) {
    u64 d; asm("fma.rn.f32x2 %0, %1, %2, %3;" : "=l"(d) : "l"(a), "l"(b), "l"(c));
    return d;
}

// --- 1D kernel extraction: 2D kernel is outer product k1*k1^T with sum(k1)=1,
// so row-sums recover k1 exactly (up to fp32 rounding). Store (k,k) pairs. ---
__global__ void k1d_kernel(const float* __restrict__ k2d) {
    int i = threadIdx.x;
    if (i < KS) {
        float s = 0.f;
        #pragma unroll
        for (int j = 0; j < KS; j++) s += k2d[i * KS + j];
        g_kpair[i] = pack2(s, s);
    }
}

__device__ __forceinline__ int reflect_idx(int i, int n) {
    // jnp.pad mode='reflect' (mirror WITHOUT repeating the edge)
    if (i < 0)  i = -i;
    if (i >= n) i = 2 * n - 2 - i;
    return i;
}

// ====== Horizontal conv: row-pair f32x2, sliding window, R=5 ================
// Block = 8 warps; each warp owns ONE row-pair and a 160-wide x tile
// (32 lanes x 5 consecutive outputs). 1920 = 12*160 exact; 6480 rows = 3240
// pairs (planes are even-height so pairs never straddle planes).
// Data LDS.64 at u64-index 5*lane+t: half-warp banks {10L,10L+1} mod 32 are
// distinct -> conflict-free. Weights come from __constant__ (uniform port).
#define HR     5
#define HTILE  (32 * HR)          // 160
#define HWARPS 8
#define HWIN   (HTILE + 2 * RAD)  // 210

__global__ void __launch_bounds__(256, 4) hconv_kernel(const float* __restrict__ in,
                                                       float* __restrict__ out) {
    __shared__ u64 s2[HWARPS][HWIN + 1];
    const int tid = threadIdx.x, lane = tid & 31, wp = tid >> 5;
    const int rp = blockIdx.y * HWARPS + wp;        // row-pair index
    const int x0 = blockIdx.x * HTILE;

    const float* r0 = in + (size_t)(2 * rp) * W;
    const float* r1 = r0 + W;
    for (int i = lane; i < HWIN; i += 32) {
        int x = reflect_idx(x0 - RAD + i, W);
        s2[wp][i] = pack2(r0[x], r1[x]);
    }
    __syncwarp();

    const int o = lane * HR;
    u64 w[HR], acc[HR];
    #pragma unroll
    for (int j = 0; j < HR; j++) { w[j] = s2[wp][o + j]; acc[j] = 0ull; }

    #pragma unroll
    for (int t = 0; t < KS; t++) {
        u64 k = c_kpair[t];
        #pragma unroll
        for (int r = 0; r < HR; r++) acc[r] = fma2(k, w[r], acc[r]);
        if (t < KS - 1) {
            #pragma unroll
            for (int j = 0; j < HR - 1; j++) w[j] = w[j + 1];
            w[HR - 1] = s2[wp][o + t + HR];
        }
    }

    float* o0 = out + (size_t)(2 * rp) * W + x0 + o;
    float* o1 = o0 + W;
    #pragma unroll
    for (int r = 0; r < HR; r++) {
        float a, b; unpack2(acc[r], a, b);
        o0[r] = a; o1[r] = b;
    }
}

// ====== Vertical conv: column-pair f32x2, sliding window, R=8 ===============
// Block (32,8): 32 lanes = 32 u64 columns (64 scalar cols, contiguous ->
// native 64-bit LDG/LDS/STG). Each thread computes 8 consecutive y outputs.
#define VR    8
#define VTY   8
#define VTILE (VR * VTY)          // 64 rows per block
#define VWIN  (VTILE + 2 * RAD)   // 114

// Pass 3: blur = Vconv(tmpA); fused residual/mask. blur->d_out, mask->tmpB.
__global__ void __launch_bounds__(256, 4) vconv_mask_kernel(const u64* __restrict__ in,
                                                            const u64* __restrict__ img,
                                                            u64* __restrict__ blur_out,
                                                            u64* __restrict__ mask_out) {
    __shared__ u64 st[VWIN][32];
    const int tx = threadIdx.x, ty = threadIdx.y;
    const int c  = blockIdx.x * 32 + tx;      // u64 column, < W2
    const int y0 = blockIdx.y * VTILE;
    const size_t pb = (size_t)blockIdx.z * (HWSZ / 2);

    for (int i = ty; i < VWIN; i += VTY) {
        int y = reflect_idx(y0 - RAD + i, H);
        st[i][tx] = in[pb + (size_t)y * W2 + c];
    }
    __syncthreads();

    const int yb = ty * VR;
    u64 w[VR], acc[VR];
    #pragma unroll
    for (int j = 0; j < VR; j++) { w[j] = st[yb + j][tx]; acc[j] = 0ull; }

    #pragma unroll
    for (int t = 0; t < KS; t++) {
        u64 k = c_kpair[t];
        #pragma unroll
        for (int r = 0; r < VR; r++) acc[r] = fma2(k, w[r], acc[r]);
        if (t < KS - 1) {
            #pragma unroll
            for (int j = 0; j < VR - 1; j++) w[j] = w[j + 1];
            w[VR - 1] = st[yb + t + VR][tx];
        }
    }

    #pragma unroll
    for (int r = 0; r < VR; r++) {
        int y = y0 + yb + r;
        if (y < H) {
            size_t idx = pb + (size_t)y * W2 + c;
            float bx, by, ix, iy;
            unpack2(acc[r], bx, by);
            unpack2(img[idx], ix, iy);
            blur_out[idx] = acc[r];
            float mx = (fabsf(ix - bx) * 255.0f > 10.0f) ? 1.0f : 0.0f;
            float my = (fabsf(iy - by) * 255.0f > 10.0f) ? 1.0f : 0.0f;
            mask_out[idx] = pack2(mx, my);
        }
    }
}

// Pass 5: soft_mask = Vconv(tmpC); fused final blend. blur read/written in the
// same buffer at the same index per thread -> no restrict on that pointer.
__global__ void __launch_bounds__(256, 4) vconv_final_kernel(const u64* __restrict__ in,
                                                             const u64* __restrict__ img,
                                                             u64* blur_and_out) {
    __shared__ u64 st[VWIN][32];
    const int tx = threadIdx.x, ty = threadIdx.y;
    const int c  = blockIdx.x * 32 + tx;
    const int y0 = blockIdx.y * VTILE;
    const size_t pb = (size_t)blockIdx.z * (HWSZ / 2);

    for (int i = ty; i < VWIN; i += VTY) {
        int y = reflect_idx(y0 - RAD + i, H);
        st[i][tx] = in[pb + (size_t)y * W2 + c];
    }
    __syncthreads();

    const int yb = ty * VR;
    u64 w[VR], acc[VR];
    #pragma unroll
    for (int j = 0; j < VR; j++) { w[j] = st[yb + j][tx]; acc[j] = 0ull; }

    #pragma unroll
    for (int t = 0; t < KS; t++) {
        u64 k = c_kpair[t];
        #pragma unroll
        for (int r = 0; r < VR; r++) acc[r] = fma2(k, w[r], acc[r]);
        if (t < KS - 1) {
            #pragma unroll
            for (int j = 0; j < VR - 1; j++) w[j] = w[j + 1];
            w[VR - 1] = st[yb + t + VR][tx];
        }
    }

    #pragma unroll
    for (int r = 0; r < VR; r++) {
        int y = y0 + yb + r;
        if (y < H) {
            size_t idx = pb + (size_t)y * W2 + c;
            float sx, sy, ix, iy, bx, by;
            unpack2(acc[r], sx, sy);
            unpack2(img[idx], ix, iy);
            unpack2(blur_and_out[idx], bx, by);
            float shx = fminf(fmaxf(fmaf(0.5f, ix - bx, ix), 0.0f), 1.0f);
            float shy = fminf(fmaxf(fmaf(0.5f, iy - by, iy), 0.0f), 1.0f);
            float ox = sx * shx + (1.0f - sx) * ix;
            float oy = sy * shy + (1.0f - sy) * iy;
            blur_and_out[idx] = pack2(ox, oy);
        }
    }
}

extern "C" void kernel_launch(void* const* d_in, const int* in_sizes, int n_in,
                              void* d_out, int out_size) {
    const float* img = (const float*)d_in[0];   // [2,3,1080,1920] fp32
    const float* k2d = (const float*)d_in[1];   // [51,51] fp32
    float* out = (float*)d_out;

    float *tmpA, *tmpB, *tmpC;
    u64* kpair;
    cudaGetSymbolAddress((void**)&tmpA, g_tmpA);
    cudaGetSymbolAddress((void**)&tmpB, g_tmpB);
    cudaGetSymbolAddress((void**)&tmpC, g_tmpC);
    cudaGetSymbolAddress((void**)&kpair, g_kpair);

    // 1) recover 1D kernel as (k,k) pairs, then stage into __constant__
    k1d_kernel<<<1, 64>>>(k2d);
    cudaMemcpyToSymbolAsync(c_kpair, kpair, KS * sizeof(u64), 0,
                            cudaMemcpyDeviceToDevice);

    dim3 hgrid(W / HTILE, (NPL * H / 2) / HWARPS);       // (12, 405)
    dim3 vgrid(W2 / 32, (H + VTILE - 1) / VTILE, NPL);   // (30, 17, 6)
    dim3 vblk(32, VTY);

    // 2) horizontal blur of img
    hconv_kernel<<<hgrid, 256>>>(img, tmpA);
    // 3) vertical blur -> blur (d_out) + mask (tmpB)
    vconv_mask_kernel<<<vgrid, vblk>>>((const u64*)tmpA, (const u64*)img,
                                       (u64*)out, (u64*)tmpB);
    // 4) horizontal blur of mask
    hconv_kernel<<<hgrid, 256>>>(tmpB, tmpC);
    // 5) vertical blur of mask + final blend -> d_out
    vconv_final_kernel<<<vgrid, vblk>>>((const u64*)tmpC, (const u64*)img,
                                        (u64*)out);
}